// round 16
// baseline (speedup 1.0000x reference)
#include <cuda_runtime.h>
#include <cuda_bf16.h>
#include <math.h>
#include <stdint.h>

#define HWDIM 128
#define NSP   16384   // 128*128
#define BATCH 2
#define HEADS 4
#define NCHUNK 16
#define CHUNK  1024
#define TS     128
#define HP    130     // padded image height
#define WP    132     // padded image width (4B-word units)

// ---------------- scratch (static device memory; no allocations) ----------------
// packed weights (tap-major k): [chunk][Cout][16] u32 words, word=(k even, k odd) bf16x2
__device__ uint32_t g_wqkv_h[4   * 384 * 16];
__device__ uint32_t g_wqkv_l[4   * 384 * 16];
__device__ uint32_t g_wdw_h [108 * 384 * 16];
__device__ uint32_t g_wdw_l [108 * 384 * 16];
__device__ uint32_t g_wpo_h [4   * 128 * 16];
__device__ uint32_t g_wpo_l [4   * 128 * 16];
// packed padded images: [B][C/2][HP][WP] u32, word = (ch even, ch odd) bf16x2
__device__ uint32_t g_px_h[(size_t)BATCH * 64  * HP * WP];
__device__ uint32_t g_px_l[(size_t)BATCH * 64  * HP * WP];
__device__ uint32_t g_pq_h[(size_t)BATCH * 192 * HP * WP];
__device__ uint32_t g_pq_l[(size_t)BATCH * 192 * HP * WP];
__device__ uint32_t g_pa_h[(size_t)BATCH * 64  * HP * WP];
__device__ uint32_t g_pa_l[(size_t)BATCH * 64  * HP * WP];
__device__ float g_buf1[(size_t)BATCH * 384 * NSP];
__device__ float g_buf2[(size_t)BATCH * 384 * NSP];
__device__ float g_Gp [NCHUNK * BATCH * HEADS * 32 * 32];
__device__ float g_qnp[NCHUNK * BATCH * HEADS * 32];
__device__ float g_knp[NCHUNK * BATCH * HEADS * 32];
__device__ float g_attn[BATCH * HEADS * 32 * 32];

__constant__ int   c_cidx[16] = {0,1,2,3, 1,0,3,2, 2,3,0,1, 3,2,1,0};
__constant__ float c_sign[16] = {1,-1,-1,-1, 1,1,-1,1, 1,1,1,-1, 1,-1,1,1};

// ---------------- helpers ----------------
__device__ __forceinline__ uint32_t packbf(float a, float b) {
    __nv_bfloat162 t = __floats2bfloat162_rn(a, b);
    return *reinterpret_cast<uint32_t*>(&t);
}
__device__ __forceinline__ float bfres(float f) {
    return f - __bfloat162float(__float2bfloat16_rn(f));
}
__device__ __forceinline__ void mma_bf16(float* c, const uint32_t* a, const uint32_t* b) {
    asm volatile(
        "mma.sync.aligned.m16n8k16.row.col.f32.bf16.bf16.f32 "
        "{%0,%1,%2,%3}, {%4,%5,%6,%7}, {%8,%9}, {%0,%1,%2,%3};"
        : "+f"(c[0]), "+f"(c[1]), "+f"(c[2]), "+f"(c[3])
        : "r"(a[0]), "r"(a[1]), "r"(a[2]), "r"(a[3]), "r"(b[0]), "r"(b[1]));
}
__device__ __forceinline__ void ldm_x4(uint32_t* r, uint32_t saddr) {
    asm volatile("ldmatrix.sync.aligned.m8n8.x4.shared.b16 {%0,%1,%2,%3}, [%4];"
        : "=r"(r[0]), "=r"(r[1]), "=r"(r[2]), "=r"(r[3]) : "r"(saddr));
}
__device__ __forceinline__ void cp16(uint32_t* dst, const uint32_t* src) {
    uint32_t d = (uint32_t)__cvta_generic_to_shared(dst);
    asm volatile("cp.async.cg.shared.global [%0], [%1], 16;" :: "r"(d), "l"(src));
}
__device__ __forceinline__ void cp4(uint32_t* dst, const uint32_t* src) {
    uint32_t d = (uint32_t)__cvta_generic_to_shared(dst);
    asm volatile("cp.async.ca.shared.global [%0], [%1], 4;" :: "r"(d), "l"(src));
}
#define CP_COMMIT() asm volatile("cp.async.commit_group;")
#define CP_WAIT0()  asm volatile("cp.async.wait_group 0;" ::: "memory")

// ---------------- build packed quaternion weight (tap-major k, bf16 hi/lo) ------
__global__ void build_weight_pack(const float* __restrict__ r, const float* __restrict__ i,
                                  const float* __restrict__ j, const float* __restrict__ k,
                                  uint32_t* __restrict__ Wh, uint32_t* __restrict__ Wl,
                                  int Po, int Pi, int KHW) {
    const float* comps[4] = {r, i, j, k};
    const int Cout = 4 * Po;
    const int Cin  = 4 * Pi;
    const int K = Cin * KHW;
    const int total = Cout * (K >> 1);
    for (int idx = blockIdx.x * blockDim.x + threadIdx.x; idx < total;
         idx += gridDim.x * blockDim.x) {
        int c   = idx / (Cout * 16);
        int rem = idx - c * Cout * 16;
        int m   = rem >> 4;
        int kwl = rem & 15;
        int k0  = c * 32 + kwl * 2;          // tap-major: k = tap*Cin + ch
        int tap = k0 / Cin, ch = k0 - tap * Cin;
        float w01[2];
        #pragma unroll
        for (int e = 0; e < 2; e++) {
            int cc = ch + e;
            int t = (m / Po) * 4 + (cc / Pi);
            w01[e] = c_sign[t] * comps[c_cidx[t]][((m % Po) * Pi + (cc % Pi)) * KHW + tap];
        }
        Wh[idx] = packbf(w01[0], w01[1]);
        Wl[idx] = packbf(bfres(w01[0]), bfres(w01[1]));
    }
}

// ---------------- pack fp32 image -> padded channel-pair bf16x2 hi/lo planes ----
__global__ void pack_image(const float* __restrict__ in, uint32_t* __restrict__ ph,
                           uint32_t* __restrict__ pl, int C2) {
    const int total = BATCH * C2 * HP * WP;
    int idx = blockIdx.x * blockDim.x + threadIdx.x;
    if (idx >= total) return;
    int xp = idx % WP;
    int t1 = idx / WP;
    int yp = t1 % HP;
    int t2 = t1 / HP;
    int c2 = t2 % C2;
    int b  = t2 / C2;
    int y = yp - 1, x = xp - 1;
    float v0 = 0.f, v1 = 0.f;
    if ((unsigned)y < 128u && (unsigned)x < 128u) {
        const float* p = in + ((size_t)(b * 2 * C2 + 2 * c2) << 14) + (y << 7) + x;
        v0 = p[0];
        v1 = p[NSP];
    }
    ph[idx] = packbf(v0, v1);
    pl[idx] = packbf(bfres(v0), bfres(v1));
}

// ---------------- bf16x3-split implicit-GEMM conv, fully pre-packed -------------
// acc = Wh*Xh + Wh*Xl + Wl*Xh ; CTA 128m x 64n x 32k chunks; 8 warps (2m x 4n).
// A: prepacked bf16 via cp.async(16B) + ldmatrix.x4. B: prepacked padded image,
// pure cp.async(4B) shifted-window reads. No cvt/predication in the loop.
#define A_STW 20      // words per A row: 16 + 4 pad
#define B_STW 72      // words per B kw-row: 64 n + 8 pad
#define A_PLANE 2560  // 128 * A_STW words
#define B_PLANE 1152  // 16 * B_STW words
#define SMEM_WORDS (4 * A_PLANE + 4 * B_PLANE)   // 59392 B

template <int KS>
__global__ void __launch_bounds__(256, 2)
conv_mma(const uint32_t* __restrict__ Wh, const uint32_t* __restrict__ Wl,
         const uint32_t* __restrict__ pbh, const uint32_t* __restrict__ pbl,
         const float* __restrict__ bias, float* __restrict__ out,
         int Cout, int Cin) {
    extern __shared__ uint32_t sm[];
    const int K   = Cin * KS * KS;
    const int NC  = K / 32;
    const int CPT = Cin / 32;        // chunks per tap
    const int b   = blockIdx.z;
    const int m0  = blockIdx.y * 128, n0 = blockIdx.x * 64;
    const int y0  = n0 >> 7, x0 = n0 & 127;
    const size_t planewords = (size_t)(Cin >> 1) * HP * WP;
    const uint32_t* imh = pbh + (size_t)b * planewords;
    const uint32_t* iml = pbl + (size_t)b * planewords;

    const int tid  = threadIdx.x;
    const int w    = tid >> 5, lane = tid & 31;
    const int gid  = lane >> 2, tig = lane & 3;
    const int mw   = (w >> 2) * 64;
    const int nw   = (w & 3) * 16;

    // B cp.async mapping: thread -> (plane, kw row, 8 n-words)
    const int bp  = tid >> 7;          // 0 = hi, 1 = lo
    const int bkw = (tid >> 3) & 15;   // 0..15
    const int bn8 = (tid & 7) * 8;     // 0..56

    // ldmatrix lane address (bytes)
    const uint32_t sm_u32 = (uint32_t)__cvta_generic_to_shared(sm);
    const int lg = lane >> 3, lr = lane & 7;
    const uint32_t a_lane_off =
        (((mw + (lg & 1) * 8 + lr) * A_STW) + (lg >> 1) * 4) * 4;

    auto loadAB = [&](int c, int s) {
        // A: 128m x 16 words, hi+lo planes
        const uint32_t* srcH = Wh + ((size_t)c * Cout + m0) * 16;
        const uint32_t* srcL = Wl + ((size_t)c * Cout + m0) * 16;
        uint32_t* dH = sm + (s * 2 + 0) * A_PLANE;
        uint32_t* dL = sm + (s * 2 + 1) * A_PLANE;
        #pragma unroll
        for (int i2 = 0; i2 < 2; i2++) {
            int u = tid * 2 + i2;
            int row = u >> 2, sub = (u & 3) * 4;
            cp16(dH + row * A_STW + sub, srcH + row * 16 + sub);
            cp16(dL + row * A_STW + sub, srcL + row * 16 + sub);
        }
        // B: shifted window of the packed padded image
        int tap = c / CPT;
        int dy = (KS == 1) ? 1 : (tap / 3);
        int dx = (KS == 1) ? 1 : (tap - (tap / 3) * 3);
        int ch2 = (c - tap * CPT) * 16 + bkw;
        const uint32_t* src = (bp ? iml : imh) +
            ((size_t)ch2 * HP + (y0 + dy)) * WP + (x0 + dx) + bn8;
        uint32_t* dst = sm + 4 * A_PLANE + (s * 2 + bp) * B_PLANE + bkw * B_STW + bn8;
        #pragma unroll
        for (int i2 = 0; i2 < 8; i2++) cp4(dst + i2, src + i2);
    };

    float acc[4][2][4] = {};

    loadAB(0, 0);
    CP_COMMIT();
    CP_WAIT0();
    __syncthreads();

    for (int c = 0; c < NC; c++) {
        const int s = c & 1;
        const bool more = (c + 1 < NC);
        if (more) { loadAB(c + 1, s ^ 1); CP_COMMIT(); }

        const uint32_t aH32 = sm_u32 + (s * 2 + 0) * A_PLANE * 4;
        const uint32_t aL32 = sm_u32 + (s * 2 + 1) * A_PLANE * 4;
        const uint32_t* BsH = sm + 4 * A_PLANE + (s * 2 + 0) * B_PLANE;
        const uint32_t* BsL = sm + 4 * A_PLANE + (s * 2 + 1) * B_PLANE;

        #pragma unroll
        for (int ks = 0; ks < 2; ks++) {
            const int kw0 = ks * 8;
            uint32_t ah[4][4], al[4][4], bh[2][2], bl[2][2];
            #pragma unroll
            for (int mt = 0; mt < 4; mt++) {
                uint32_t off = a_lane_off + mt * (16 * A_STW * 4) + kw0 * 4;
                ldm_x4(ah[mt], aH32 + off);
                ldm_x4(al[mt], aL32 + off);
            }
            #pragma unroll
            for (int nt = 0; nt < 2; nt++) {
                int nc0 = nw + nt * 8 + gid;
                bh[nt][0] = BsH[(kw0 + tig) * B_STW + nc0];
                bh[nt][1] = BsH[(kw0 + tig + 4) * B_STW + nc0];
                bl[nt][0] = BsL[(kw0 + tig) * B_STW + nc0];
                bl[nt][1] = BsL[(kw0 + tig + 4) * B_STW + nc0];
            }
            #pragma unroll
            for (int mt = 0; mt < 4; mt++)
                #pragma unroll
                for (int nt = 0; nt < 2; nt++)
                    mma_bf16(acc[mt][nt], ah[mt], bh[nt]);
            #pragma unroll
            for (int mt = 0; mt < 4; mt++)
                #pragma unroll
                for (int nt = 0; nt < 2; nt++)
                    mma_bf16(acc[mt][nt], ah[mt], bl[nt]);
            #pragma unroll
            for (int mt = 0; mt < 4; mt++)
                #pragma unroll
                for (int nt = 0; nt < 2; nt++)
                    mma_bf16(acc[mt][nt], al[mt], bh[nt]);
        }

        if (more) CP_WAIT0();
        __syncthreads();
    }

    // epilogue: direct fragment stores (+bias)
    float* outb = out + (size_t)b * Cout * NSP;
    #pragma unroll
    for (int mt = 0; mt < 4; mt++) {
        int m = m0 + mw + mt * 16 + gid;
        float bs0 = bias[m], bs1 = bias[m + 8];
        #pragma unroll
        for (int nt = 0; nt < 2; nt++) {
            int n = n0 + nw + nt * 8 + tig * 2;
            float2 v0 = make_float2(acc[mt][nt][0] + bs0, acc[mt][nt][1] + bs0);
            float2 v1 = make_float2(acc[mt][nt][2] + bs1, acc[mt][nt][3] + bs1);
            *(float2*)&outb[(size_t)m * NSP + n]       = v0;
            *(float2*)&outb[(size_t)(m + 8) * NSP + n] = v1;
        }
    }
}

// ---------------- attention stage 1: partial Gram + norms (deterministic) ------
__global__ void attn_partial(const float* __restrict__ qkv) {
    const int b = blockIdx.z, h = blockIdx.y, chunk = blockIdx.x;
    const float* q = qkv + ((size_t)b * 384 + h * 32) * NSP;
    const float* k = qkv + ((size_t)b * 384 + 128 + h * 32) * NSP;

    __shared__ float qs[32][TS + 1];
    __shared__ float ks[32][TS + 1];

    const int tid = threadIdx.x;
    const int e0 = tid * 4;
    const int ci = e0 >> 5;
    const int cj0 = e0 & 31;

    float acc[4] = {};
    float qn = 0.f, kn = 0.f;
    const int sbase0 = chunk * CHUNK;

    for (int t = 0; t < CHUNK / TS; t++) {
        int sbase = sbase0 + t * TS;
        for (int l = tid; l < 32 * TS; l += 256) {
            int c = l / TS, ss = l % TS;
            qs[c][ss] = q[(size_t)c * NSP + sbase + ss];
            ks[c][ss] = k[(size_t)c * NSP + sbase + ss];
        }
        __syncthreads();
        #pragma unroll 4
        for (int ss = 0; ss < TS; ss++) {
            float qv = qs[ci][ss];
            acc[0] += qv * ks[cj0 + 0][ss];
            acc[1] += qv * ks[cj0 + 1][ss];
            acc[2] += qv * ks[cj0 + 2][ss];
            acc[3] += qv * ks[cj0 + 3][ss];
        }
        if (tid < 32) {
            for (int ss = 0; ss < TS; ss++) {
                float a = qs[tid][ss]; qn += a * a;
                float c2 = ks[tid][ss]; kn += c2 * c2;
            }
        }
        __syncthreads();
    }

    int bh = b * HEADS + h;
    float* Gp = g_Gp + ((size_t)chunk * BATCH * HEADS + bh) * 1024;
    Gp[e0 + 0] = acc[0]; Gp[e0 + 1] = acc[1];
    Gp[e0 + 2] = acc[2]; Gp[e0 + 3] = acc[3];
    if (tid < 32) {
        g_qnp[((size_t)chunk * BATCH * HEADS + bh) * 32 + tid] = qn;
        g_knp[((size_t)chunk * BATCH * HEADS + bh) * 32 + tid] = kn;
    }
}

// ---------------- attention stage 2: reduce, normalize, softmax ----------------
__global__ void attn_finalize(const float* __restrict__ temperature) {
    const int b = blockIdx.y, h = blockIdx.x;
    const int bh = b * HEADS + h;
    const int ci = threadIdx.x;

    __shared__ float qn_s[32], kn_s[32];
    float qn = 0.f, kn = 0.f;
    for (int c = 0; c < NCHUNK; c++) {
        qn += g_qnp[((size_t)c * BATCH * HEADS + bh) * 32 + ci];
        kn += g_knp[((size_t)c * BATCH * HEADS + bh) * 32 + ci];
    }
    qn_s[ci] = fmaxf(sqrtf(qn), 1e-12f);
    kn_s[ci] = fmaxf(sqrtf(kn), 1e-12f);
    __syncwarp();

    float T = temperature[h];
    float qi = qn_s[ci];
    float lg[32];
    float mx = -1e30f;
    #pragma unroll
    for (int cj = 0; cj < 32; cj++) {
        float g = 0.f;
        for (int c = 0; c < NCHUNK; c++)
            g += g_Gp[(((size_t)c * BATCH * HEADS + bh) * 1024) + ci * 32 + cj];
        float v = g / (qi * kn_s[cj]) * T;
        lg[cj] = v;
        mx = fmaxf(mx, v);
    }
    float s = 0.f;
    #pragma unroll
    for (int cj = 0; cj < 32; cj++) { lg[cj] = __expf(lg[cj] - mx); s += lg[cj]; }
    float inv = 1.f / s;
    float* A = g_attn + (size_t)bh * 1024;
    #pragma unroll
    for (int cj = 0; cj < 32; cj++) A[ci * 32 + cj] = lg[cj] * inv;
}

// ---------------- attention stage 3: out = attn @ v ----------------
__global__ void attn_apply(const float* __restrict__ qkv, float* __restrict__ out) {
    const int b = blockIdx.z, h = blockIdx.y;
    const int s = blockIdx.x * 256 + threadIdx.x;
    __shared__ float A[1024];
    for (int l = threadIdx.x; l < 1024; l += 256)
        A[l] = g_attn[((size_t)(b * HEADS + h)) * 1024 + l];
    __syncthreads();

    const float* v = qkv + ((size_t)b * 384 + 256 + h * 32) * NSP;
    float acc[32] = {};
    #pragma unroll 4
    for (int cj = 0; cj < 32; cj++) {
        float vv = v[(size_t)cj * NSP + s];
        #pragma unroll
        for (int ci = 0; ci < 32; ci++) acc[ci] += A[ci * 32 + cj] * vv;
    }
    float* ob = out + ((size_t)b * 128 + h * 32) * NSP;
    #pragma unroll
    for (int ci = 0; ci < 32; ci++) ob[(size_t)ci * NSP + s] = acc[ci];
}

// ---------------- launch ----------------
extern "C" void kernel_launch(void* const* d_in, const int* in_sizes, int n_in,
                              void* d_out, int out_size) {
    const float* x      = (const float*)d_in[0];
    const float* qkv_r  = (const float*)d_in[1];
    const float* qkv_i  = (const float*)d_in[2];
    const float* qkv_j  = (const float*)d_in[3];
    const float* qkv_k  = (const float*)d_in[4];
    const float* qkv_b  = (const float*)d_in[5];
    const float* dw_r   = (const float*)d_in[6];
    const float* dw_i   = (const float*)d_in[7];
    const float* dw_j   = (const float*)d_in[8];
    const float* dw_k   = (const float*)d_in[9];
    const float* dw_b   = (const float*)d_in[10];
    const float* po_r   = (const float*)d_in[11];
    const float* po_i   = (const float*)d_in[12];
    const float* po_j   = (const float*)d_in[13];
    const float* po_k   = (const float*)d_in[14];
    const float* po_b   = (const float*)d_in[15];
    const float* temp   = (const float*)d_in[16];
    float* out = (float*)d_out;

    uint32_t *wqh, *wql, *wdh, *wdl, *wph, *wpl;
    uint32_t *pxh, *pxl, *pqh, *pql, *pah, *pal;
    float *buf1, *buf2;
    cudaGetSymbolAddress((void**)&wqh, g_wqkv_h);
    cudaGetSymbolAddress((void**)&wql, g_wqkv_l);
    cudaGetSymbolAddress((void**)&wdh, g_wdw_h);
    cudaGetSymbolAddress((void**)&wdl, g_wdw_l);
    cudaGetSymbolAddress((void**)&wph, g_wpo_h);
    cudaGetSymbolAddress((void**)&wpl, g_wpo_l);
    cudaGetSymbolAddress((void**)&pxh, g_px_h);
    cudaGetSymbolAddress((void**)&pxl, g_px_l);
    cudaGetSymbolAddress((void**)&pqh, g_pq_h);
    cudaGetSymbolAddress((void**)&pql, g_pq_l);
    cudaGetSymbolAddress((void**)&pah, g_pa_h);
    cudaGetSymbolAddress((void**)&pal, g_pa_l);
    cudaGetSymbolAddress((void**)&buf1, g_buf1);
    cudaGetSymbolAddress((void**)&buf2, g_buf2);

    const int smem_bytes = SMEM_WORDS * 4;
    cudaFuncSetAttribute(conv_mma<1>, cudaFuncAttributeMaxDynamicSharedMemorySize, smem_bytes);
    cudaFuncSetAttribute(conv_mma<3>, cudaFuncAttributeMaxDynamicSharedMemorySize, smem_bytes);

    // 1) materialize packed quaternion weights (tap-major, bf16x2 hi/lo)
    build_weight_pack<<<96, 256>>>(qkv_r, qkv_i, qkv_j, qkv_k, wqh, wql, 96, 32, 1);
    build_weight_pack<<<2592, 256>>>(dw_r, dw_i, dw_j, dw_k, wdh, wdl, 96, 96, 9);
    build_weight_pack<<<32, 256>>>(po_r, po_i, po_j, po_k, wph, wpl, 32, 32, 1);

    // 2) pack x, then qkv 1x1 conv -> buf1 fp32
    {
        int total = BATCH * 64 * HP * WP;
        pack_image<<<(total + 255) / 256, 256>>>(x, pxh, pxl, 64);
    }
    conv_mma<1><<<dim3(NSP / 64, 3, BATCH), 256, smem_bytes>>>(wqh, wql, pxh, pxl, qkv_b, buf1, 384, 128);

    // 3) pack buf1, then dw 3x3 conv -> buf2 fp32
    {
        int total = BATCH * 192 * HP * WP;
        pack_image<<<(total + 255) / 256, 256>>>(buf1, pqh, pql, 192);
    }
    conv_mma<3><<<dim3(NSP / 64, 3, BATCH), 256, smem_bytes>>>(wdh, wdl, pqh, pql, dw_b, buf2, 384, 384);

    // 4) channel attention -> buf1 fp32 [B,128,NSP]
    attn_partial<<<dim3(NCHUNK, HEADS, BATCH), 256>>>(buf2);
    attn_finalize<<<dim3(HEADS, BATCH), 32>>>(temp);
    attn_apply<<<dim3(NSP / 256, HEADS, BATCH), 256>>>(buf2, buf1);

    // 5) pack attn out, then po 1x1 conv -> d_out
    {
        int total = BATCH * 64 * HP * WP;
        pack_image<<<(total + 255) / 256, 256>>>(buf1, pah, pal, 64);
    }
    conv_mma<1><<<dim3(NSP / 64, 1, BATCH), 256, smem_bytes>>>(wph, wpl, pah, pal, po_b, out, 128, 128);
}

// round 17
// speedup vs baseline: 1.4797x; 1.4797x over previous
#include <cuda_runtime.h>
#include <cuda_bf16.h>
#include <math.h>
#include <stdint.h>

#define HWDIM 128
#define NSP   16384   // 128*128
#define BATCH 2
#define HEADS 4
#define NCHUNK 16
#define CHUNK  1024
#define TS     128

// ---------------- scratch (static device memory; no allocations) ----------------
// packed weights: [chunk][Cout][16] uint32 words, word = bf16x2 (k even lo, k odd hi)
__device__ uint32_t g_wqkv_h[4   * 384 * 16];
__device__ uint32_t g_wqkv_l[4   * 384 * 16];
__device__ uint32_t g_wdw_h [108 * 384 * 16];
__device__ uint32_t g_wdw_l [108 * 384 * 16];
__device__ uint32_t g_wpo_h [4   * 128 * 16];
__device__ uint32_t g_wpo_l [4   * 128 * 16];
__device__ float g_buf1[(size_t)BATCH * 384 * NSP];
__device__ float g_buf2[(size_t)BATCH * 384 * NSP];
__device__ float g_Gp [NCHUNK * BATCH * HEADS * 32 * 32];
__device__ float g_qnp[NCHUNK * BATCH * HEADS * 32];
__device__ float g_knp[NCHUNK * BATCH * HEADS * 32];
__device__ float g_attn[BATCH * HEADS * 32 * 32];

__constant__ int   c_cidx[16] = {0,1,2,3, 1,0,3,2, 2,3,0,1, 3,2,1,0};
__constant__ float c_sign[16] = {1,-1,-1,-1, 1,1,-1,1, 1,1,1,-1, 1,-1,1,1};

// ---------------- helpers ----------------
__device__ __forceinline__ uint32_t packbf(float a, float b) {
    __nv_bfloat162 t = __floats2bfloat162_rn(a, b);
    return *reinterpret_cast<uint32_t*>(&t);
}
__device__ __forceinline__ float bfres(float f) {
    return f - __bfloat162float(__float2bfloat16_rn(f));
}
__device__ __forceinline__ void mma_bf16(float* c, const uint32_t* a, const uint32_t* b) {
    asm volatile(
        "mma.sync.aligned.m16n8k16.row.col.f32.bf16.bf16.f32 "
        "{%0,%1,%2,%3}, {%4,%5,%6,%7}, {%8,%9}, {%0,%1,%2,%3};"
        : "+f"(c[0]), "+f"(c[1]), "+f"(c[2]), "+f"(c[3])
        : "r"(a[0]), "r"(a[1]), "r"(a[2]), "r"(a[3]), "r"(b[0]), "r"(b[1]));
}
__device__ __forceinline__ void ldm_x4(uint32_t* r, uint32_t saddr) {
    asm volatile("ldmatrix.sync.aligned.m8n8.x4.shared.b16 {%0,%1,%2,%3}, [%4];"
        : "=r"(r[0]), "=r"(r[1]), "=r"(r[2]), "=r"(r[3]) : "r"(saddr));
}
__device__ __forceinline__ void cp16(uint32_t* dst, const uint32_t* src) {
    uint32_t d = (uint32_t)__cvta_generic_to_shared(dst);
    asm volatile("cp.async.cg.shared.global [%0], [%1], 16;" :: "r"(d), "l"(src));
}
#define CP_COMMIT() asm volatile("cp.async.commit_group;")
#define CP_WAIT0()  asm volatile("cp.async.wait_group 0;" ::: "memory")

// ---------------- build packed quaternion weight (bf16x2 hi/lo planes) ----------
__global__ void build_weight_pack(const float* __restrict__ r, const float* __restrict__ i,
                                  const float* __restrict__ j, const float* __restrict__ k,
                                  uint32_t* __restrict__ Wh, uint32_t* __restrict__ Wl,
                                  int Po, int Pi, int KHW) {
    const float* comps[4] = {r, i, j, k};
    const int Cout = 4 * Po;
    const int K = 4 * Pi * KHW;
    const int total = Cout * (K >> 1);
    for (int idx = blockIdx.x * blockDim.x + threadIdx.x; idx < total;
         idx += gridDim.x * blockDim.x) {
        int c   = idx / (Cout * 16);
        int rem = idx - c * Cout * 16;
        int m   = rem >> 4;
        int kwl = rem & 15;
        int k0  = c * 32 + kwl * 2;
        float w01[2];
        #pragma unroll
        for (int e = 0; e < 2; e++) {
            int kcol = k0 + e;
            int cc = kcol / KHW, khw = kcol - cc * KHW;
            int t = (m / Po) * 4 + (cc / Pi);
            w01[e] = c_sign[t] * comps[c_cidx[t]][((m % Po) * Pi + (cc % Pi)) * KHW + khw];
        }
        Wh[idx] = packbf(w01[0], w01[1]);
        Wl[idx] = packbf(bfres(w01[0]), bfres(w01[1]));
    }
}

// ---------------- bf16x3-split implicit-GEMM conv, pipelined ----------------
// acc = Wh*Xh + Wh*Xl + Wl*Xh ; CTA 128m x 64n x 32k chunks.
// 8 warps as 4m x 2n, warp tile 32m x 32n (small acc -> 3 CTAs/SM).
// A: prepacked bf16 via cp.async + ldmatrix.x4. B: LDG fp32 -> cvt -> STS.
#define A_STW 20      // words per A row: 16 + 4 pad
#define B_STW 72      // words per B kw-row: 64 n + 8 pad
#define A_PLANE 2560  // 128 * A_STW words
#define B_PLANE 1152  // 16 * B_STW words
#define SMEM_WORDS (4 * A_PLANE + 4 * B_PLANE)   // 59392 B

template <int KS, int PAD>
__global__ void __launch_bounds__(256, 3)
conv_mma(const uint32_t* __restrict__ Wh, const uint32_t* __restrict__ Wl,
         const float* __restrict__ in, const float* __restrict__ bias,
         float* __restrict__ out, int Cout, int Cin) {
    extern __shared__ uint32_t sm[];
    const int K  = Cin * KS * KS;
    const int NC = K / 32;
    const int b  = blockIdx.z;
    const int m0 = blockIdx.y * 128, n0 = blockIdx.x * 64;
    const float* inb = in + (size_t)b * Cin * NSP;

    const int tid  = threadIdx.x;
    const int w    = tid >> 5, lane = tid & 31;
    const int gid  = lane >> 2, tig = lane & 3;
    const int mw   = (w >> 1) * 32;   // warp m offset (0/32/64/96)
    const int nw   = (w & 1) * 32;    // warp n offset (0/32)

    // B loader indexing: one thread = (kw row, 4 n)
    const int kwl = tid >> 4;          // 0..15
    const int nf4 = (tid & 15) * 4;    // 0..60

    // ldmatrix lane address (bytes): matrices (lg&1)->m8 row block, (lg>>1)->k half
    const uint32_t sm_u32 = (uint32_t)__cvta_generic_to_shared(sm);
    const int lg = lane >> 3, lr = lane & 7;
    const uint32_t a_lane_off =
        (((mw + (lg & 1) * 8 + lr) * A_STW) + (lg >> 1) * 4) * 4;

    float fB[2][4];   // B prefetch fp32: [k parity][n]

    auto loadA = [&](int c, int s) {
        const uint32_t* srcH = Wh + ((size_t)c * Cout + m0) * 16;
        const uint32_t* srcL = Wl + ((size_t)c * Cout + m0) * 16;
        uint32_t* dH = sm + (s * 2 + 0) * A_PLANE;
        uint32_t* dL = sm + (s * 2 + 1) * A_PLANE;
        #pragma unroll
        for (int i2 = 0; i2 < 2; i2++) {
            int u = tid * 2 + i2;
            int row = u >> 2, sub = (u & 3) * 4;
            cp16(dH + row * A_STW + sub, srcH + row * 16 + sub);
            cp16(dL + row * A_STW + sub, srcL + row * 16 + sub);
        }
    };

    auto loadB = [&](int k0) {
        #pragma unroll
        for (int kp = 0; kp < 2; kp++) {
            int kk = k0 + kwl * 2 + kp;
            if (KS == 1) {
                float4 xv = *(const float4*)&inb[(size_t)kk * NSP + n0 + nf4];
                fB[kp][0] = xv.x; fB[kp][1] = xv.y; fB[kp][2] = xv.z; fB[kp][3] = xv.w;
            } else {
                int cch = kk / 9;
                int rem = kk - cch * 9;
                int ky = rem / 3, kx = rem - ky * 3;
                int n = n0 + nf4;
                int y = n >> 7, x = n & 127;
                int iy = y + ky - PAD;
                bool yok = (unsigned)iy < (unsigned)HWDIM;
                const float* rowp = inb + ((size_t)cch << 14) + ((size_t)iy << 7);
                int ix0 = x + kx - PAD;
                #pragma unroll
                for (int i2 = 0; i2 < 4; i2++)
                    fB[kp][i2] = (yok && (unsigned)(ix0 + i2) < 128u)
                                     ? __ldg(rowp + ix0 + i2) : 0.f;
            }
        }
    };

    auto stsB = [&](int s) {
        uint32_t* dH = sm + 4 * A_PLANE + (s * 2 + 0) * B_PLANE;
        uint32_t* dL = sm + 4 * A_PLANE + (s * 2 + 1) * B_PLANE;
        uint4 hw, lw;
        hw.x = packbf(fB[0][0], fB[1][0]);
        hw.y = packbf(fB[0][1], fB[1][1]);
        hw.z = packbf(fB[0][2], fB[1][2]);
        hw.w = packbf(fB[0][3], fB[1][3]);
        lw.x = packbf(bfres(fB[0][0]), bfres(fB[1][0]));
        lw.y = packbf(bfres(fB[0][1]), bfres(fB[1][1]));
        lw.z = packbf(bfres(fB[0][2]), bfres(fB[1][2]));
        lw.w = packbf(bfres(fB[0][3]), bfres(fB[1][3]));
        *(uint4*)&dH[kwl * B_STW + nf4] = hw;
        *(uint4*)&dL[kwl * B_STW + nf4] = lw;
    };

    float acc[2][4][4] = {};

    // prologue: fill stage 0
    loadA(0, 0);
    CP_COMMIT();
    loadB(0);
    stsB(0);
    CP_WAIT0();
    __syncthreads();

    for (int c = 0; c < NC; c++) {
        const int s = c & 1;
        const bool more = (c + 1 < NC);
        if (more) {
            loadA(c + 1, s ^ 1);
            CP_COMMIT();
            loadB((c + 1) * 32);
        }

        const uint32_t aH32 = sm_u32 + (s * 2 + 0) * A_PLANE * 4;
        const uint32_t aL32 = sm_u32 + (s * 2 + 1) * A_PLANE * 4;
        const uint32_t* BsH = sm + 4 * A_PLANE + (s * 2 + 0) * B_PLANE;
        const uint32_t* BsL = sm + 4 * A_PLANE + (s * 2 + 1) * B_PLANE;

        #pragma unroll
        for (int ks = 0; ks < 2; ks++) {
            const int kw0 = ks * 8;
            uint32_t ah[2][4], al[2][4], bh[4][2], bl[4][2];
            #pragma unroll
            for (int mt = 0; mt < 2; mt++) {
                uint32_t off = a_lane_off + mt * (16 * A_STW * 4) + kw0 * 4;
                ldm_x4(ah[mt], aH32 + off);
                ldm_x4(al[mt], aL32 + off);
            }
            #pragma unroll
            for (int nt = 0; nt < 4; nt++) {
                int nc0 = nw + nt * 8 + gid;
                bh[nt][0] = BsH[(kw0 + tig) * B_STW + nc0];
                bh[nt][1] = BsH[(kw0 + tig + 4) * B_STW + nc0];
                bl[nt][0] = BsL[(kw0 + tig) * B_STW + nc0];
                bl[nt][1] = BsL[(kw0 + tig + 4) * B_STW + nc0];
            }
            // term-outer ordering: accumulator reuse distance = 8 MMAs
            #pragma unroll
            for (int mt = 0; mt < 2; mt++)
                #pragma unroll
                for (int nt = 0; nt < 4; nt++)
                    mma_bf16(acc[mt][nt], ah[mt], bh[nt]);
            #pragma unroll
            for (int mt = 0; mt < 2; mt++)
                #pragma unroll
                for (int nt = 0; nt < 4; nt++)
                    mma_bf16(acc[mt][nt], ah[mt], bl[nt]);
            #pragma unroll
            for (int mt = 0; mt < 2; mt++)
                #pragma unroll
                for (int nt = 0; nt < 4; nt++)
                    mma_bf16(acc[mt][nt], al[mt], bh[nt]);
        }

        if (more) stsB(s ^ 1);
        CP_WAIT0();
        __syncthreads();
    }

    // epilogue: direct fragment stores (+bias)
    float* outb = out + (size_t)b * Cout * NSP;
    #pragma unroll
    for (int mt = 0; mt < 2; mt++) {
        int m = m0 + mw + mt * 16 + gid;
        float bs0 = bias[m], bs1 = bias[m + 8];
        #pragma unroll
        for (int nt = 0; nt < 4; nt++) {
            int n = n0 + nw + nt * 8 + tig * 2;
            float2 v0 = make_float2(acc[mt][nt][0] + bs0, acc[mt][nt][1] + bs0);
            float2 v1 = make_float2(acc[mt][nt][2] + bs1, acc[mt][nt][3] + bs1);
            *(float2*)&outb[(size_t)m * NSP + n]       = v0;
            *(float2*)&outb[(size_t)(m + 8) * NSP + n] = v1;
        }
    }
}

// ---------------- attention stage 1: partial Gram + norms (deterministic) ------
__global__ void attn_partial(const float* __restrict__ qkv) {
    const int b = blockIdx.z, h = blockIdx.y, chunk = blockIdx.x;
    const float* q = qkv + ((size_t)b * 384 + h * 32) * NSP;
    const float* k = qkv + ((size_t)b * 384 + 128 + h * 32) * NSP;

    __shared__ float qs[32][TS + 1];
    __shared__ float ks[32][TS + 1];

    const int tid = threadIdx.x;
    const int e0 = tid * 4;
    const int ci = e0 >> 5;
    const int cj0 = e0 & 31;

    float acc[4] = {};
    float qn = 0.f, kn = 0.f;
    const int sbase0 = chunk * CHUNK;

    for (int t = 0; t < CHUNK / TS; t++) {
        int sbase = sbase0 + t * TS;
        for (int l = tid; l < 32 * TS; l += 256) {
            int c = l / TS, ss = l % TS;
            qs[c][ss] = q[(size_t)c * NSP + sbase + ss];
            ks[c][ss] = k[(size_t)c * NSP + sbase + ss];
        }
        __syncthreads();
        #pragma unroll 4
        for (int ss = 0; ss < TS; ss++) {
            float qv = qs[ci][ss];
            acc[0] += qv * ks[cj0 + 0][ss];
            acc[1] += qv * ks[cj0 + 1][ss];
            acc[2] += qv * ks[cj0 + 2][ss];
            acc[3] += qv * ks[cj0 + 3][ss];
        }
        if (tid < 32) {
            for (int ss = 0; ss < TS; ss++) {
                float a = qs[tid][ss]; qn += a * a;
                float c2 = ks[tid][ss]; kn += c2 * c2;
            }
        }
        __syncthreads();
    }

    int bh = b * HEADS + h;
    float* Gp = g_Gp + ((size_t)chunk * BATCH * HEADS + bh) * 1024;
    Gp[e0 + 0] = acc[0]; Gp[e0 + 1] = acc[1];
    Gp[e0 + 2] = acc[2]; Gp[e0 + 3] = acc[3];
    if (tid < 32) {
        g_qnp[((size_t)chunk * BATCH * HEADS + bh) * 32 + tid] = qn;
        g_knp[((size_t)chunk * BATCH * HEADS + bh) * 32 + tid] = kn;
    }
}

// ---------------- attention stage 2: reduce, normalize, softmax ----------------
__global__ void attn_finalize(const float* __restrict__ temperature) {
    const int b = blockIdx.y, h = blockIdx.x;
    const int bh = b * HEADS + h;
    const int ci = threadIdx.x;

    __shared__ float qn_s[32], kn_s[32];
    float qn = 0.f, kn = 0.f;
    for (int c = 0; c < NCHUNK; c++) {
        qn += g_qnp[((size_t)c * BATCH * HEADS + bh) * 32 + ci];
        kn += g_knp[((size_t)c * BATCH * HEADS + bh) * 32 + ci];
    }
    qn_s[ci] = fmaxf(sqrtf(qn), 1e-12f);
    kn_s[ci] = fmaxf(sqrtf(kn), 1e-12f);
    __syncwarp();

    float T = temperature[h];
    float qi = qn_s[ci];
    float lg[32];
    float mx = -1e30f;
    #pragma unroll
    for (int cj = 0; cj < 32; cj++) {
        float g = 0.f;
        for (int c = 0; c < NCHUNK; c++)
            g += g_Gp[(((size_t)c * BATCH * HEADS + bh) * 1024) + ci * 32 + cj];
        float v = g / (qi * kn_s[cj]) * T;
        lg[cj] = v;
        mx = fmaxf(mx, v);
    }
    float s = 0.f;
    #pragma unroll
    for (int cj = 0; cj < 32; cj++) { lg[cj] = __expf(lg[cj] - mx); s += lg[cj]; }
    float inv = 1.f / s;
    float* A = g_attn + (size_t)bh * 1024;
    #pragma unroll
    for (int cj = 0; cj < 32; cj++) A[ci * 32 + cj] = lg[cj] * inv;
}

// ---------------- attention stage 3: out = attn @ v ----------------
__global__ void attn_apply(const float* __restrict__ qkv, float* __restrict__ out) {
    const int b = blockIdx.z, h = blockIdx.y;
    const int s = blockIdx.x * 256 + threadIdx.x;
    __shared__ float A[1024];
    for (int l = threadIdx.x; l < 1024; l += 256)
        A[l] = g_attn[((size_t)(b * HEADS + h)) * 1024 + l];
    __syncthreads();

    const float* v = qkv + ((size_t)b * 384 + 256 + h * 32) * NSP;
    float acc[32] = {};
    #pragma unroll 4
    for (int cj = 0; cj < 32; cj++) {
        float vv = v[(size_t)cj * NSP + s];
        #pragma unroll
        for (int ci = 0; ci < 32; ci++) acc[ci] += A[ci * 32 + cj] * vv;
    }
    float* ob = out + ((size_t)b * 128 + h * 32) * NSP;
    #pragma unroll
    for (int ci = 0; ci < 32; ci++) ob[(size_t)ci * NSP + s] = acc[ci];
}

// ---------------- launch ----------------
extern "C" void kernel_launch(void* const* d_in, const int* in_sizes, int n_in,
                              void* d_out, int out_size) {
    const float* x      = (const float*)d_in[0];
    const float* qkv_r  = (const float*)d_in[1];
    const float* qkv_i  = (const float*)d_in[2];
    const float* qkv_j  = (const float*)d_in[3];
    const float* qkv_k  = (const float*)d_in[4];
    const float* qkv_b  = (const float*)d_in[5];
    const float* dw_r   = (const float*)d_in[6];
    const float* dw_i   = (const float*)d_in[7];
    const float* dw_j   = (const float*)d_in[8];
    const float* dw_k   = (const float*)d_in[9];
    const float* dw_b   = (const float*)d_in[10];
    const float* po_r   = (const float*)d_in[11];
    const float* po_i   = (const float*)d_in[12];
    const float* po_j   = (const float*)d_in[13];
    const float* po_k   = (const float*)d_in[14];
    const float* po_b   = (const float*)d_in[15];
    const float* temp   = (const float*)d_in[16];
    float* out = (float*)d_out;

    uint32_t *wqh, *wql, *wdh, *wdl, *wph, *wpl;
    float *buf1, *buf2;
    cudaGetSymbolAddress((void**)&wqh, g_wqkv_h);
    cudaGetSymbolAddress((void**)&wql, g_wqkv_l);
    cudaGetSymbolAddress((void**)&wdh, g_wdw_h);
    cudaGetSymbolAddress((void**)&wdl, g_wdw_l);
    cudaGetSymbolAddress((void**)&wph, g_wpo_h);
    cudaGetSymbolAddress((void**)&wpl, g_wpo_l);
    cudaGetSymbolAddress((void**)&buf1, g_buf1);
    cudaGetSymbolAddress((void**)&buf2, g_buf2);

    const int smem_bytes = SMEM_WORDS * 4;
    cudaFuncSetAttribute(conv_mma<1, 0>, cudaFuncAttributeMaxDynamicSharedMemorySize, smem_bytes);
    cudaFuncSetAttribute(conv_mma<3, 1>, cudaFuncAttributeMaxDynamicSharedMemorySize, smem_bytes);

    // 1) materialize packed quaternion weights (bf16x2 hi/lo, MMA layout)
    build_weight_pack<<<96, 256>>>(qkv_r, qkv_i, qkv_j, qkv_k, wqh, wql, 96, 32, 1);
    build_weight_pack<<<2592, 256>>>(dw_r, dw_i, dw_j, dw_k, wdh, wdl, 96, 96, 9);
    build_weight_pack<<<32, 256>>>(po_r, po_i, po_j, po_k, wph, wpl, 32, 32, 1);

    // 2) qkv 1x1 conv: [B,128,NSP] -> [B,384,NSP]
    conv_mma<1, 0><<<dim3(NSP / 64, 3, BATCH), 256, smem_bytes>>>(wqh, wql, x, qkv_b, buf1, 384, 128);

    // 3) dw 3x3 conv: [B,384,NSP] -> [B,384,NSP]
    conv_mma<3, 1><<<dim3(NSP / 64, 3, BATCH), 256, smem_bytes>>>(wdh, wdl, buf1, dw_b, buf2, 384, 384);

    // 4) channel attention
    attn_partial<<<dim3(NCHUNK, HEADS, BATCH), 256>>>(buf2);
    attn_finalize<<<dim3(HEADS, BATCH), 32>>>(temp);
    attn_apply<<<dim3(NSP / 256, HEADS, BATCH), 256>>>(buf2, buf1);

    // 5) po 1x1 conv: [B,128,NSP] -> d_out
    conv_mma<1, 0><<<dim3(NSP / 64, 1, BATCH), 256, smem_bytes>>>(wph, wpl, buf1, po_b, out, 128, 128);
}